// round 15
// baseline (speedup 1.0000x reference)
#include <cuda_runtime.h>
#include <cuda_bf16.h>

// ---------------------------------------------------------------------------
// GatedDeltaNet (B=2,T=4096,D=1024,H=16,DK=DV=64,KS=4)
// Round 15: scan -> 256 threads + double-buffered chunk matrices (loads
// overlap compute); prep substitution 4-way ILP. Rest = round-14 winner.
// ---------------------------------------------------------------------------

#define TDIM 4096
#define BDIM 2
#define HDIM 16
#define DDIM 1024
#define MROWS (BDIM * TDIM)
#define NCHUNK 64
#define NCH_TOT (BDIM * HDIM * NCHUNK)   // 2048

typedef unsigned long long ull;
typedef unsigned int uint;

static constexpr size_t NM   = (size_t)MROWS * DDIM;
static constexpr size_t OF_Q  = 0;
static constexpr size_t OF_K  = 1 * NM;
static constexpr size_t OF_V  = 2 * NM;
static constexpr size_t OF_QN = 3 * NM;
static constexpr size_t OF_KN = 4 * NM;
static constexpr size_t OF_VN = 5 * NM;
static constexpr size_t OF_G  = 6 * NM;
static constexpr size_t OF_O  = 7 * NM;
static constexpr size_t OF_OG = 8 * NM;
static constexpr size_t OF_XG = 9 * NM;
static constexpr size_t OF_A  = OF_XG + (size_t)MROWS * 512;
static constexpr size_t OF_B  = OF_A + (size_t)MROWS * HDIM;
static constexpr size_t CHMAT = (size_t)NCH_TOT * 4096;
static constexpr size_t OF_PG  = OF_B + (size_t)MROWS * HDIM;
static constexpr size_t OF_AQG = OF_PG + CHMAT;
static constexpr size_t OF_GKT = OF_AQG + CHMAT;
static constexpr size_t OF_WTG = OF_GKT + CHMAT;
static constexpr size_t OF_UVT = OF_WTG + CHMAT;
static constexpr size_t OF_ACG = OF_UVT + CHMAT;
static constexpr size_t SCRATCH_FLOATS = OF_ACG + NCH_TOT;

__device__ float g_scratch[SCRATCH_FLOATS];

__device__ __forceinline__ float sigmoidf_(float x) {
    return 1.f / (1.f + __expf(-x));
}
__device__ __forceinline__ ull fma2_(ull a, ull b, ull c) {
    ull d;
    asm("fma.rn.f32x2 %0, %1, %2, %3;" : "=l"(d) : "l"(a), "l"(b), "l"(c));
    return d;
}
__device__ __forceinline__ float hadd2_(ull a) {
    unsigned lo, hi;
    asm("mov.b64 {%0, %1}, %2;" : "=r"(lo), "=r"(hi) : "l"(a));
    return __uint_as_float(lo) + __uint_as_float(hi);
}
__device__ __forceinline__ void mma_bf16(float c[4],
    uint a0, uint a1, uint a2, uint a3, uint b0, uint b1)
{
    asm volatile(
        "mma.sync.aligned.m16n8k16.row.col.f32.bf16.bf16.f32 "
        "{%0,%1,%2,%3},{%4,%5,%6,%7},{%8,%9},{%0,%1,%2,%3};"
        : "+f"(c[0]), "+f"(c[1]), "+f"(c[2]), "+f"(c[3])
        : "r"(a0), "r"(a1), "r"(a2), "r"(a3), "r"(b0), "r"(b1));
}
__device__ __forceinline__ void ldsm_x4(uint& r0, uint& r1, uint& r2, uint& r3,
                                        const void* p)
{
    uint a = (uint)__cvta_generic_to_shared(p);
    asm volatile("ldmatrix.sync.aligned.m8n8.x4.shared.b16 {%0,%1,%2,%3},[%4];"
                 : "=r"(r0), "=r"(r1), "=r"(r2), "=r"(r3) : "r"(a));
}
__device__ __forceinline__ void ldsm_x2t(uint& r0, uint& r1, const void* p)
{
    uint a = (uint)__cvta_generic_to_shared(p);
    asm volatile("ldmatrix.sync.aligned.m8n8.x2.trans.shared.b16 {%0,%1},[%2];"
                 : "=r"(r0), "=r"(r1) : "r"(a));
}
__device__ __forceinline__ void split4(float4 v, uint& h01, uint& h23,
                                       uint& l01, uint& l23)
{
    __nv_bfloat162 h01b = __floats2bfloat162_rn(v.x, v.y);
    __nv_bfloat162 h23b = __floats2bfloat162_rn(v.z, v.w);
    float r0 = v.x - __bfloat162float(h01b.x);
    float r1 = v.y - __bfloat162float(h01b.y);
    float r2 = v.z - __bfloat162float(h23b.x);
    float r3 = v.w - __bfloat162float(h23b.y);
    __nv_bfloat162 l01b = __floats2bfloat162_rn(r0, r1);
    __nv_bfloat162 l23b = __floats2bfloat162_rn(r2, r3);
    h01 = *(uint*)&h01b;  h23 = *(uint*)&h23b;
    l01 = *(uint*)&l01b;  l23 = *(uint*)&l23b;
}

#define A_STRIDE 12
#define B_STRIDE 68

__global__ __launch_bounds__(256) void gemm_tc(
    const float* __restrict__ Aext, size_t Aoff,
    const float* __restrict__ W0, const float* __restrict__ W1,
    const float* __restrict__ W2,
    float* __restrict__ Cext, size_t Coff, int nblk,
    int M, int N, int K, int act)
{
    const float* A = Aext ? Aext : (const float*)g_scratch + Aoff;
    const int which = blockIdx.x / nblk;
    const float* W = (which == 0) ? W0 : (which == 1) ? W1 : W2;
    float* C = Cext ? Cext : g_scratch + Coff + (size_t)which * NM;

    __shared__ __align__(16) uint As[2][2][128][A_STRIDE];
    __shared__ __align__(16) uint Bs[2][2][16][B_STRIDE];

    const int tid  = threadIdx.x;
    const int brow = blockIdx.y * 128;
    const int bcol = (blockIdx.x % nblk) * 128;
    const int lane = tid & 31;
    const int warp = tid >> 5;
    const int wm   = warp >> 2;
    const int wn   = warp & 3;
    const int gid  = lane >> 2;
    const int tig  = lane & 3;
    const int am0 = tid >> 2;
    const int ak0 = (tid & 3) << 2;
    const int bk0 = tid >> 5;
    const int bn0 = (tid & 31) << 2;

    const float* ApA = A + (size_t)(brow + am0) * K + ak0;
    const float* ApB = ApA + (size_t)64 * K;
    const float* BpA = W + (size_t)bk0 * N + bcol + bn0;
    const float* BpB = BpA + (size_t)8 * N;

    float acc[4][4][4];
#pragma unroll
    for (int i = 0; i < 4; i++)
#pragma unroll
        for (int j = 0; j < 4; j++)
#pragma unroll
            for (int c = 0; c < 4; c++) acc[i][j][c] = 0.f;

    const int a_lrow = lane & 15;
    const int a_koff = (lane >> 4) * 4;
    const int b_lrow = lane & 15;

    float4 avA, avB, bvA, bvB;
    avA = *(const float4*)(ApA);
    avB = *(const float4*)(ApB);
    bvA = *(const float4*)(BpA);
    bvB = *(const float4*)(BpB);
    {
        uint h01, h23, l01, l23;
        split4(avA, h01, h23, l01, l23);
        *(uint2*)&As[0][0][am0][ak0 >> 1]      = make_uint2(h01, h23);
        *(uint2*)&As[0][1][am0][ak0 >> 1]      = make_uint2(l01, l23);
        split4(avB, h01, h23, l01, l23);
        *(uint2*)&As[0][0][am0 + 64][ak0 >> 1] = make_uint2(h01, h23);
        *(uint2*)&As[0][1][am0 + 64][ak0 >> 1] = make_uint2(l01, l23);
        split4(bvA, h01, h23, l01, l23);
        *(uint2*)&Bs[0][0][bk0][bn0 >> 1]      = make_uint2(h01, h23);
        *(uint2*)&Bs[0][1][bk0][bn0 >> 1]      = make_uint2(l01, l23);
        split4(bvB, h01, h23, l01, l23);
        *(uint2*)&Bs[0][0][bk0 + 8][bn0 >> 1]  = make_uint2(h01, h23);
        *(uint2*)&Bs[0][1][bk0 + 8][bn0 >> 1]  = make_uint2(l01, l23);
    }
    __syncthreads();

    const int nk = K >> 4;
    for (int kt = 0; kt < nk; kt++) {
        const int buf = kt & 1;
        if (kt + 1 < nk) {
            const int ko = (kt + 1) << 4;
            avA = *(const float4*)(ApA + ko);
            avB = *(const float4*)(ApB + ko);
            bvA = *(const float4*)(BpA + (size_t)ko * N);
            bvB = *(const float4*)(BpB + (size_t)ko * N);
        }
        uint Ah[4][4], Al[4][4], Bh[4][2], Bl[4][2];
#pragma unroll
        for (int mt = 0; mt < 4; mt++) {
            int row = wm * 64 + mt * 16 + a_lrow;
            ldsm_x4(Ah[mt][0], Ah[mt][1], Ah[mt][2], Ah[mt][3],
                    &As[buf][0][row][a_koff]);
            ldsm_x4(Al[mt][0], Al[mt][1], Al[mt][2], Al[mt][3],
                    &As[buf][1][row][a_koff]);
        }
#pragma unroll
        for (int nt = 0; nt < 4; nt++) {
            int nu = wn * 16 + nt * 4;
            ldsm_x2t(Bh[nt][0], Bh[nt][1], &Bs[buf][0][b_lrow][nu]);
            ldsm_x2t(Bl[nt][0], Bl[nt][1], &Bs[buf][1][b_lrow][nu]);
        }
#pragma unroll
        for (int mt = 0; mt < 4; mt++) {
#pragma unroll
            for (int nt = 0; nt < 4; nt++) {
                mma_bf16(acc[mt][nt], Ah[mt][0], Ah[mt][1], Ah[mt][2], Ah[mt][3],
                         Bh[nt][0], Bh[nt][1]);
                mma_bf16(acc[mt][nt], Ah[mt][0], Ah[mt][1], Ah[mt][2], Ah[mt][3],
                         Bl[nt][0], Bl[nt][1]);
                mma_bf16(acc[mt][nt], Al[mt][0], Al[mt][1], Al[mt][2], Al[mt][3],
                         Bh[nt][0], Bh[nt][1]);
            }
        }
        if (kt + 1 < nk) {
            const int nb = buf ^ 1;
            uint h01, h23, l01, l23;
            split4(avA, h01, h23, l01, l23);
            *(uint2*)&As[nb][0][am0][ak0 >> 1]      = make_uint2(h01, h23);
            *(uint2*)&As[nb][1][am0][ak0 >> 1]      = make_uint2(l01, l23);
            split4(avB, h01, h23, l01, l23);
            *(uint2*)&As[nb][0][am0 + 64][ak0 >> 1] = make_uint2(h01, h23);
            *(uint2*)&As[nb][1][am0 + 64][ak0 >> 1] = make_uint2(l01, l23);
            split4(bvA, h01, h23, l01, l23);
            *(uint2*)&Bs[nb][0][bk0][bn0 >> 1]      = make_uint2(h01, h23);
            *(uint2*)&Bs[nb][1][bk0][bn0 >> 1]      = make_uint2(l01, l23);
            split4(bvB, h01, h23, l01, l23);
            *(uint2*)&Bs[nb][0][bk0 + 8][bn0 >> 1]  = make_uint2(h01, h23);
            *(uint2*)&Bs[nb][1][bk0 + 8][bn0 >> 1]  = make_uint2(l01, l23);
            __syncthreads();
        }
    }
#pragma unroll
    for (int mt = 0; mt < 4; mt++) {
        int row0 = brow + wm * 64 + mt * 16 + gid;
#pragma unroll
        for (int nt = 0; nt < 4; nt++) {
            int col0 = bcol + wn * 32 + nt * 8 + 2 * tig;
            float c0 = acc[mt][nt][0], c1 = acc[mt][nt][1];
            float c2 = acc[mt][nt][2], c3 = acc[mt][nt][3];
            if (act == 1) {
                c0 *= sigmoidf_(c0); c1 *= sigmoidf_(c1);
                c2 *= sigmoidf_(c2); c3 *= sigmoidf_(c3);
            } else if (act == 2) {
                c0 = sigmoidf_(c0); c1 = sigmoidf_(c1);
                c2 = sigmoidf_(c2); c3 = sigmoidf_(c3);
            }
            *(float2*)(C + (size_t)row0 * N + col0)       = make_float2(c0, c1);
            *(float2*)(C + (size_t)(row0 + 8) * N + col0) = make_float2(c2, c3);
        }
    }
}

__global__ __launch_bounds__(256) void ab_kernel(
    const float* __restrict__ x,
    const float* __restrict__ Wa, const float* __restrict__ ba,
    const float* __restrict__ Wb, const float* __restrict__ bb)
{
    int row  = blockIdx.x * 8 + (threadIdx.x >> 5);
    int lane = threadIdx.x & 31;
    const float* xr = x + (size_t)row * DDIM;
    const float* W  = (lane < 16) ? Wa : Wb;
    int h = lane & 15;
    float s0 = 0.f, s1 = 0.f, s2 = 0.f, s3 = 0.f;
#pragma unroll 4
    for (int i = 0; i < DDIM; i += 4) {
        s0 = fmaf(xr[i + 0], W[(i + 0) * HDIM + h], s0);
        s1 = fmaf(xr[i + 1], W[(i + 1) * HDIM + h], s1);
        s2 = fmaf(xr[i + 2], W[(i + 2) * HDIM + h], s2);
        s3 = fmaf(xr[i + 3], W[(i + 3) * HDIM + h], s3);
    }
    float s = (s0 + s1) + (s2 + s3);
    if (lane < 16) {
        float sg = sigmoidf_(s + ba[h]);
        g_scratch[OF_A + (size_t)row * HDIM + h] = fminf(fmaxf(sg, 0.1f), 1.0f);
    } else {
        float sg = sigmoidf_(s + bb[h]);
        g_scratch[OF_B + (size_t)row * HDIM + h] = fminf(sg, 1.0f);
    }
}

__global__ __launch_bounds__(512) void conv_kernel(
    const float* __restrict__ qcw, const float* __restrict__ qcb,
    const float* __restrict__ kcw, const float* __restrict__ kcb,
    const float* __restrict__ vcw, const float* __restrict__ vcb)
{
    int which = blockIdx.y;
    const float* w;
    const float* bias;
    size_t pre_off, out_off;
    int do_norm;
    if (which == 0) { w = qcw; bias = qcb; pre_off = OF_Q; out_off = OF_QN; do_norm = 1; }
    else if (which == 1) { w = kcw; bias = kcb; pre_off = OF_K; out_off = OF_KN; do_norm = 1; }
    else { w = vcw; bias = vcb; pre_off = OF_V; out_off = OF_VN; do_norm = 0; }

    const float* pre = (const float*)g_scratch + pre_off;
    float*       out = g_scratch + out_off;
    int row  = blockIdx.x;
    int t    = row & (TDIM - 1);
    int lane = threadIdx.x & 31;
    int h    = threadIdx.x >> 5;
    int c0   = h * 64 + lane;
    int c1   = c0 + 32;

    const float* p = pre + (size_t)row * DDIM;
    float v0 = bias[c0], v1 = bias[c1];
#pragma unroll
    for (int kk = 0; kk < 4; kk++) {
        int dt = kk - 3;
        if (t + dt >= 0) {
            const float* pr = p + (ptrdiff_t)dt * DDIM;
            v0 = fmaf(w[c0 * 4 + kk], pr[c0], v0);
            v1 = fmaf(w[c1 * 4 + kk], pr[c1], v1);
        }
    }
    v0 *= sigmoidf_(v0);
    v1 *= sigmoidf_(v1);
    if (do_norm) {
        float ss = v0 * v0 + v1 * v1;
#pragma unroll
        for (int o = 16; o > 0; o >>= 1) ss += __shfl_xor_sync(0xffffffffu, ss, o);
        float inv = 1.f / fmaxf(sqrtf(ss), 1e-6f);
        v0 *= inv; v1 *= inv;
    }
    out[(size_t)row * DDIM + c0] = v0;
    out[(size_t)row * DDIM + c1] = v1;
}

// ---------------------------------------------------------------------------
// prep_kernel (round-14 + 4-way ILP substitution)
// ---------------------------------------------------------------------------
__global__ __launch_bounds__(256) void prep_kernel()
{
    extern __shared__ float sm[];
    float* Kc  = sm;
    float* Qv  = sm + 4352;
    float* MM  = sm + 8704;
    float* sLc = sm + 13056;
    float* sLp = sm + 13120;
    float* sbv = sm + 13184;
    float* sbp = sm + 13248;
    float* E2  = sm + 13312;
    float* Ei2 = sm + 13376;
    float* E2p = sm + 13440;
    float* A0  = sm + 13504;
    float* G0  = sm + 13568;

    const float* Qn = g_scratch + OF_QN;
    const float* Kn = g_scratch + OF_KN;
    const float* Vn = g_scratch + OF_VN;
    const float* Al = g_scratch + OF_A;
    const float* Be = g_scratch + OF_B;

    int cid = blockIdx.x;
    int bh = cid >> 6, ci = cid & 63;
    int b = bh >> 4, h = bh & 15;
    int t0c = ci << 6;
    size_t base  = (size_t)b * TDIM * DDIM + (size_t)h * 64 + (size_t)t0c * DDIM;
    size_t abase = (size_t)b * TDIM * HDIM + h + (size_t)t0c * HDIM;
    int tid = threadIdx.x;

    if (tid < 64) {
        sLc[tid] = log2f(Al[abase + (size_t)tid * HDIM]);
        sbv[tid] = Be[abase + (size_t)tid * HDIM];
    }
    __syncthreads();
    if (tid == 0) {
        float run = 0.f;
        for (int i = 0; i < 64; i++) { sLp[i] = run; run += sLc[i]; sLc[i] = run; }
    }
    {
        int row = tid >> 4;
        int col = (tid & 15) << 2;
        for (int rr = 0; rr < 4; rr++) {
            int r = row + rr * 16;
            *(float4*)&Kc[r * 68 + col] = *(const float4*)(Kn + base + (size_t)r * DDIM + col);
            *(float4*)&Qv[r * 68 + col] = *(const float4*)(Qn + base + (size_t)r * DDIM + col);
        }
    }
    __syncthreads();
    if (tid < 64) {
        float lc = sLc[tid], lp = sLp[tid];
        sbp[tid] = sbv[tid] * exp2f(lp);
        E2[tid]  = exp2f(lc + 104.f);
        Ei2[tid] = exp2f(-lc - 104.f);
        E2p[tid] = exp2f(lp + 104.f);
        A0[tid]  = exp2f(lc);
        G0[tid]  = exp2f(sLc[63] - lc);
    }
    __syncthreads();

    float* Pg  = g_scratch + OF_PG  + (size_t)cid * 4096;
    float* AQg = g_scratch + OF_AQG + (size_t)cid * 4096;
    float* Gg  = g_scratch + OF_GKT + (size_t)cid * 4096;
    float* Wg  = g_scratch + OF_WTG + (size_t)cid * 4096;
    float* Ug  = g_scratch + OF_UVT + (size_t)cid * 4096;

    for (int kq = 0; kq < 16; kq++) {
        int e = kq * 256 + tid;
        int t = e >> 6, i = e & 63;
        AQg[e] = A0[t] * Qv[t * 68 + i];
        Gg[e]  = G0[i] * Kc[i * 68 + t];
    }

    {
        int tt = tid >> 4, ti = tid & 15;
        int t0 = tt << 2, i0 = ti << 2;
        if (i0 <= t0 + 3) {
            ull acc2[4][4];
#pragma unroll
            for (int a = 0; a < 4; a++)
#pragma unroll
                for (int bb2 = 0; bb2 < 4; bb2++) acc2[a][bb2] = 0ull;
#pragma unroll 8
            for (int m = 0; m < 64; m += 2) {
                ull qr[4], kr[4];
#pragma unroll
                for (int a = 0; a < 4; a++) qr[a] = *(ull*)&Qv[(t0 + a) * 68 + m];
#pragma unroll
                for (int bb2 = 0; bb2 < 4; bb2++) kr[bb2] = *(ull*)&Kc[(i0 + bb2) * 68 + m];
#pragma unroll
                for (int a = 0; a < 4; a++)
#pragma unroll
                    for (int bb2 = 0; bb2 < 4; bb2++)
                        acc2[a][bb2] = fma2_(qr[a], kr[bb2], acc2[a][bb2]);
            }
#pragma unroll
            for (int a = 0; a < 4; a++) {
                int t = t0 + a;
                float4 v;
                float e2t = E2[t];
                v.x = (i0 + 0 <= t) ? e2t * Ei2[i0 + 0] * hadd2_(acc2[a][0]) : 0.f;
                v.y = (i0 + 1 <= t) ? e2t * Ei2[i0 + 1] * hadd2_(acc2[a][1]) : 0.f;
                v.z = (i0 + 2 <= t) ? e2t * Ei2[i0 + 2] * hadd2_(acc2[a][2]) : 0.f;
                v.w = (i0 + 3 <= t) ? e2t * Ei2[i0 + 3] * hadd2_(acc2[a][3]) : 0.f;
                *(float4*)(Pg + t * 64 + i0) = v;
            }
        } else {
            float4 z = make_float4(0.f, 0.f, 0.f, 0.f);
#pragma unroll
            for (int a = 0; a < 4; a++) *(float4*)(Pg + (t0 + a) * 64 + i0) = z;
        }
    }
    __syncthreads();
    {
        int row = tid >> 4;
        int col = (tid & 15) << 2;
        for (int rr = 0; rr < 4; rr++) {
            int r = row + rr * 16;
            *(float4*)&Qv[r * 68 + col] = *(const float4*)(Vn + base + (size_t)r * DDIM + col);
        }
    }
    __syncthreads();
    {
        int tI = tid >> 4, tJ = tid & 15;
        int i0 = tI << 2, j0 = tJ << 2;
        if (j0 <= i0 + 3) {
            ull acc2[4][4];
#pragma unroll
            for (int a = 0; a < 4; a++)
#pragma unroll
                for (int bb2 = 0; bb2 < 4; bb2++) acc2[a][bb2] = 0ull;
#pragma unroll 8
            for (int m = 0; m < 64; m += 2) {
                ull ir[4], jr[4];
#pragma unroll
                for (int a = 0; a < 4; a++) ir[a] = *(ull*)&Kc[(i0 + a) * 68 + m];
#pragma unroll
                for (int bb2 = 0; bb2 < 4; bb2++) jr[bb2] = *(ull*)&Kc[(j0 + bb2) * 68 + m];
#pragma unroll
                for (int a = 0; a < 4; a++)
#pragma unroll
                    for (int bb2 = 0; bb2 < 4; bb2++)
                        acc2[a][bb2] = fma2_(ir[a], jr[bb2], acc2[a][bb2]);
            }
#pragma unroll
            for (int a = 0; a < 4; a++) {
                int i = i0 + a;
                float bi = sbv[i] * E2p[i];
#pragma unroll
                for (int bb2 = 0; bb2 < 4; bb2++) {
                    int j = j0 + bb2;
                    if (j < i)
                        MM[i * 68 + j] = bi * Ei2[j] * hadd2_(acc2[a][bb2]);
                }
            }
        }
    }
    __syncthreads();

    float xr[64];
    if (tid < 128) {
        int c = tid;
        if (c < 64) {
#pragma unroll
            for (int i = 0; i < 64; i++) xr[i] = sbv[i] * Qv[i * 68 + c];
        } else {
            int k = c - 64;
#pragma unroll
            for (int i = 0; i < 64; i++) xr[i] = sbp[i] * Kc[i * 68 + k];
        }
#pragma unroll
        for (int i = 1; i < 64; i++) {
            float a0 = 0.f, a1 = 0.f, a2 = 0.f, a3 = 0.f;
            int j = 0;
#pragma unroll
            for (; j + 3 < i; j += 4) {
                a0 = fmaf(MM[i * 68 + j],     xr[j],     a0);
                a1 = fmaf(MM[i * 68 + j + 1], xr[j + 1], a1);
                a2 = fmaf(MM[i * 68 + j + 2], xr[j + 2], a2);
                a3 = fmaf(MM[i * 68 + j + 3], xr[j + 3], a3);
            }
#pragma unroll
            for (; j < i; j++) a0 = fmaf(MM[i * 68 + j], xr[j], a0);
            xr[i] -= ((a0 + a1) + (a2 + a3));
        }
    }
    __syncthreads();
    if (tid < 64) {
        int c = tid;
#pragma unroll
        for (int i = 0; i < 64; i++) Qv[c * 68 + i] = xr[i];
    } else if (tid < 128) {
        int k = tid - 64;
#pragma unroll
        for (int i = 0; i < 64; i++) MM[i * 68 + k] = xr[i];
    }
    __syncthreads();
    for (int kq = 0; kq < 16; kq++) {
        int e = kq * 256 + tid;
        { int c = e >> 6, i = e & 63; Ug[e] = Qv[c * 68 + i]; }
        { int i = e >> 6, kk = e & 63; Wg[e] = MM[i * 68 + kk]; }
    }
    if (tid == 0) g_scratch[OF_ACG + cid] = exp2f(sLc[63]);
}

// ---------------------------------------------------------------------------
// scan_kernel: 128 CTAs, 256 threads, double-buffered chunk matrices.
// ---------------------------------------------------------------------------
__global__ __launch_bounds__(256) void scan_kernel()
{
    extern __shared__ float sm[];
    // [buf][4 matrices][64*68] + U_T[2][16*68] + S_T[16*68]
    float* mat[2] = { sm, sm + 17408 };
    float* UTb[2] = { sm + 34816, sm + 35904 };
    float* S_T    = sm + 36992;

    int blk = blockIdx.x;
    int bh = blk >> 2, cq = blk & 3;
    int c0 = cq << 4;
    int b = bh >> 4, h = bh & 15;
    size_t obase = (size_t)b * TDIM * DDIM + (size_t)h * 64;
    int tid = threadIdx.x;
    int cc = tid & 15, grp = tid >> 4;    // grp 0..15, 4 rows each

    for (int e = tid; e < 16 * 68; e += 256) S_T[e] = 0.f;

    float* O = g_scratch + OF_O;

    // chunk loader: 4 matrices (4096 floats each) + U slice (1024 floats)
    auto load_chunk = [&](int cid, float* m, float* UT) {
        const float* Wg  = g_scratch + OF_WTG + (size_t)cid * 4096;
        const float* AQg = g_scratch + OF_AQG + (size_t)cid * 4096;
        const float* Pg  = g_scratch + OF_PG  + (size_t)cid * 4096;
        const float* Gg  = g_scratch + OF_GKT + (size_t)cid * 4096;
        const float* Ug  = g_scratch + OF_UVT + (size_t)cid * 4096;
#pragma unroll
        for (int kq = 0; kq < 4; kq++) {
            int e4 = kq * 256 + tid;
            int r = e4 >> 4, c4 = (e4 & 15) << 2;
            *(float4*)&m[0     + r * 68 + c4] = *(const float4*)(Wg  + r * 64 + c4);
            *(float4*)&m[4352  + r * 68 + c4] = *(const float4*)(AQg + r * 64 + c4);
            *(float4*)&m[8704  + r * 68 + c4] = *(const float4*)(Pg  + r * 64 + c4);
            *(float4*)&m[13056 + r * 68 + c4] = *(const float4*)(Gg  + r * 64 + c4);
        }
        {
            int r = tid >> 4, c4 = (tid & 15) << 2;
            *(float4*)&UT[r * 68 + c4] = *(const float4*)(Ug + (size_t)(c0 + r) * 64 + c4);
        }
    };

    load_chunk(bh * 64, mat[0], UTb[0]);
    __syncthreads();

    for (int ch = 0; ch < NCHUNK; ch++) {
        const int buf = ch & 1;
        int cid = bh * 64 + ch;
        float* mW  = mat[buf];
        float* mAQ = mat[buf] + 4352;
        float* mP  = mat[buf] + 8704;
        float* mG  = mat[buf] + 13056;
        float* U_T = UTb[buf];
        float AC = g_scratch[OF_ACG + cid];

        if (ch + 1 < NCHUNK)
            load_chunk(cid + 1, mat[buf ^ 1], UTb[buf ^ 1]);

        // phase U: U_T[cc][i] -= sum_k W[i][k]*S_T[cc][k]   (rows grp*4..+3)
        {
            ull aU[4][2];
#pragma unroll
            for (int ii = 0; ii < 4; ii++) { aU[ii][0] = 0; aU[ii][1] = 0; }
#pragma unroll
            for (int k4 = 0; k4 < 16; k4++) {
                ull s01 = *(ull*)&S_T[cc * 68 + k4 * 4];
                ull s23 = *(ull*)&S_T[cc * 68 + k4 * 4 + 2];
#pragma unroll
                for (int ii = 0; ii < 4; ii++) {
                    int i = grp * 4 + ii;
                    aU[ii][0] = fma2_(*(ull*)&mW[i * 68 + k4 * 4],     s01, aU[ii][0]);
                    aU[ii][1] = fma2_(*(ull*)&mW[i * 68 + k4 * 4 + 2], s23, aU[ii][1]);
                }
            }
#pragma unroll
            for (int ii = 0; ii < 4; ii++) {
                int i = grp * 4 + ii;
                U_T[cc * 68 + i] -= (hadd2_(aU[ii][0]) + hadd2_(aU[ii][1]));
            }
        }
        // phase O1: oacc[t] = sum_k AQ[t][k]*S_T[cc][k]
        float oacc[4];
        {
            ull aO[4][2];
#pragma unroll
            for (int ii = 0; ii < 4; ii++) { aO[ii][0] = 0; aO[ii][1] = 0; }
#pragma unroll
            for (int k4 = 0; k4 < 16; k4++) {
                ull s01 = *(ull*)&S_T[cc * 68 + k4 * 4];
                ull s23 = *(ull*)&S_T[cc * 68 + k4 * 4 + 2];
#pragma unroll
                for (int ii = 0; ii < 4; ii++) {
                    int t = grp * 4 + ii;
                    aO[ii][0] = fma2_(*(ull*)&mAQ[t * 68 + k4 * 4],     s01, aO[ii][0]);
                    aO[ii][1] = fma2_(*(ull*)&mAQ[t * 68 + k4 * 4 + 2], s23, aO[ii][1]);
                }
            }
#pragma unroll
            for (int ii = 0; ii < 4; ii++)
                oacc[ii] = hadd2_(aO[ii][0]) + hadd2_(aO[ii][1]);
        }
        __syncthreads();   // U_T complete
        // phase O2 + write
        {
            ull aO[4][2];
#pragma unroll
            for (int ii = 0; ii < 4; ii++) { aO[ii][0] = 0; aO[ii][1] = 0; }
#pragma unroll
            for (int k4 = 0; k4 < 16; k4++) {
                ull u01 = *(ull*)&U_T[cc * 68 + k4 * 4];
                ull u23 = *(ull*)&U_T[cc * 68 + k4 * 4 + 2];
#pragma unroll
                for (int ii = 0; ii < 4; ii++) {
                    int t = grp * 4 + ii;
                    aO[ii][0] = fma2_(*(ull*)&mP[t * 68 + k4 * 4],     u01, aO[ii][0]);
                    aO[ii][1] = fma2_(*(ull*)&mP[t * 68 + k4 * 4 + 2], u23, aO[ii][1]);
                }
            }
#pragma unroll
            for (int ii = 0; ii < 4; ii++) {
                int t = grp * 4 + ii;
                float ov = oacc[ii] + hadd2_(aO[ii][0]) + hadd2_(aO[ii][1]);
                O[obase + (size_t)(ch * 64 + t) * DDIM + c0 + cc] = ov;
            }
        }
        // phase S
        {
            ull aS[4][2];
#pragma unroll
            for (int ii = 0; ii < 4; ii++) { aS[ii][0] = 0; aS[ii][1] = 0; }
#pragma unroll
            for (int k4 = 0; k4 < 16; k4++) {
                ull u01 = *(ull*)&U_T[cc * 68 + k4 * 4];
                ull u23 = *(ull*)&U_T[cc * 68 + k4 * 4 + 2];
#pragma unroll
                for (int ii = 0; ii < 4; ii++) {
                    int r = grp * 4 + ii;
                    aS[ii][0] = fma2_(*(ull*)&mG[r * 68 + k4 * 4],     u01, aS[ii][0]);
                    aS[ii][1] = fma2_(*(ull*)&mG[r * 68 + k4 * 4 + 2], u23, aS[ii][1]);
                }
            }
#pragma unroll
            for (int ii = 0; ii < 4; ii++) {
                int r = grp * 4 + ii;
                S_T[cc * 68 + r] = AC * S_T[cc * 68 + r]
                                   + hadd2_(aS[ii][0]) + hadd2_(aS[ii][1]);
            }
        }
        __syncthreads();
    }
}

__global__ __launch_bounds__(512) void post_kernel(const float* __restrict__ rms_w)
{
    const float* O  = g_scratch + OF_O;
    const float* G  = g_scratch + OF_G;
    float*       Og = g_scratch + OF_OG;
    int row  = blockIdx.x;
    int lane = threadIdx.x & 31;
    int h    = threadIdx.x >> 5;
    size_t i0 = (size_t)row * DDIM + h * 64 + lane;
    float v0 = O[i0], v1 = O[i0 + 32];
    float ss = v0 * v0 + v1 * v1;
#pragma unroll
    for (int o = 16; o > 0; o >>= 1) ss += __shfl_xor_sync(0xffffffffu, ss, o);
    float inv = rsqrtf(ss * (1.f / 64.f) + 1e-6f);
    v0 = v0 * inv * rms_w[h * 64 + lane]      * G[i0];
    v1 = v1 * inv * rms_w[h * 64 + lane + 32] * G[i0 + 32];
    Og[i0]      = v0;
    Og[i0 + 32] = v1;
}

extern "C" void kernel_launch(void* const* d_in, const int* in_sizes, int n_in,
                              void* d_out, int out_size)
{
    (void)in_sizes; (void)n_in; (void)out_size;
    const float* x   = (const float*)d_in[0];
    const float* Wq  = (const float*)d_in[1];
    const float* Wk  = (const float*)d_in[2];
    const float* Wv  = (const float*)d_in[3];
    const float* Wo  = (const float*)d_in[4];
    const float* Wa  = (const float*)d_in[5];
    const float* ba  = (const float*)d_in[6];
    const float* Wb  = (const float*)d_in[7];
    const float* bb  = (const float*)d_in[8];
    const float* Wgd = (const float*)d_in[9];
    const float* Wgu = (const float*)d_in[10];
    const float* rms = (const float*)d_in[11];
    const float* qcw = (const float*)d_in[12];
    const float* qcb = (const float*)d_in[13];
    const float* kcw = (const float*)d_in[14];
    const float* kcb = (const float*)d_in[15];
    const float* vcw = (const float*)d_in[16];
    const float* vcb = (const float*)d_in[17];
    float* out = (float*)d_out;

    cudaFuncSetAttribute(prep_kernel, cudaFuncAttributeMaxDynamicSharedMemorySize, 57344);
    cudaFuncSetAttribute(scan_kernel, cudaFuncAttributeMaxDynamicSharedMemorySize, 155648);

    // 1) alpha/beta
    ab_kernel<<<MROWS / 8, 256>>>(x, Wa, ba, Wb, bb);
    // 2) fused QKV projection
    {
        dim3 gqkv(24, MROWS / 128);
        gemm_tc<<<gqkv, 256>>>(x, 0, Wq, Wk, Wv, nullptr, OF_Q, 8,
                               MROWS, 1024, 1024, 0);
    }
    // 3) conv
    {
        dim3 gc(MROWS, 3);
        conv_kernel<<<gc, 512>>>(qcw, qcb, kcw, kcb, vcw, vcb);
    }
    // 4) chunk prep (parallel)  <-- ncu capture slot
    prep_kernel<<<NCH_TOT, 256, 57344>>>();
    // 5) chunk scan (double-buffered)
    scan_kernel<<<BDIM * HDIM * 4, 256, 155648>>>();
    // 6-7) gate MLP
    {
        dim3 g512g(4, MROWS / 128);
        gemm_tc<<<g512g, 256>>>(x, 0, Wgd, Wgd, Wgd, nullptr, OF_XG, 4,
                                MROWS, 512, 1024, 1);
    }
    {
        dim3 g1024g(8, MROWS / 128);
        gemm_tc<<<g1024g, 256>>>(nullptr, OF_XG, Wgu, Wgu, Wgu, nullptr, OF_G, 8,
                                 MROWS, 1024, 512, 2);
    }
    // 8) RMSNorm + gate
    post_kernel<<<MROWS, 512>>>(rms);
    // 9) output projection
    {
        dim3 g1024g(8, MROWS / 128);
        gemm_tc<<<g1024g, 256>>>(nullptr, OF_OG, Wo, Wo, Wo, out, 0, 8,
                                 MROWS, 1024, 1024, 0);
    }
}

// round 16
// speedup vs baseline: 1.3556x; 1.3556x over previous
#include <cuda_runtime.h>
#include <cuda_bf16.h>

// ---------------------------------------------------------------------------
// GatedDeltaNet (B=2,T=4096,D=1024,H=16,DK=DV=64,KS=4)
// Round 16: round-14 winner + round-15 prep (4-way ILP substitution).
// Scan reverted to round-14 (round-15 double-buffer regressed -479us).
// ---------------------------------------------------------------------------

#define TDIM 4096
#define BDIM 2
#define HDIM 16
#define DDIM 1024
#define MROWS (BDIM * TDIM)
#define NCHUNK 64
#define NCH_TOT (BDIM * HDIM * NCHUNK)   // 2048

typedef unsigned long long ull;
typedef unsigned int uint;

static constexpr size_t NM   = (size_t)MROWS * DDIM;
static constexpr size_t OF_Q  = 0;
static constexpr size_t OF_K  = 1 * NM;
static constexpr size_t OF_V  = 2 * NM;
static constexpr size_t OF_QN = 3 * NM;
static constexpr size_t OF_KN = 4 * NM;
static constexpr size_t OF_VN = 5 * NM;
static constexpr size_t OF_G  = 6 * NM;
static constexpr size_t OF_O  = 7 * NM;
static constexpr size_t OF_OG = 8 * NM;
static constexpr size_t OF_XG = 9 * NM;
static constexpr size_t OF_A  = OF_XG + (size_t)MROWS * 512;
static constexpr size_t OF_B  = OF_A + (size_t)MROWS * HDIM;
static constexpr size_t CHMAT = (size_t)NCH_TOT * 4096;
static constexpr size_t OF_PG  = OF_B + (size_t)MROWS * HDIM;
static constexpr size_t OF_AQG = OF_PG + CHMAT;
static constexpr size_t OF_GKT = OF_AQG + CHMAT;
static constexpr size_t OF_WTG = OF_GKT + CHMAT;
static constexpr size_t OF_UVT = OF_WTG + CHMAT;
static constexpr size_t OF_ACG = OF_UVT + CHMAT;
static constexpr size_t SCRATCH_FLOATS = OF_ACG + NCH_TOT;

__device__ float g_scratch[SCRATCH_FLOATS];

__device__ __forceinline__ float sigmoidf_(float x) {
    return 1.f / (1.f + __expf(-x));
}
__device__ __forceinline__ ull fma2_(ull a, ull b, ull c) {
    ull d;
    asm("fma.rn.f32x2 %0, %1, %2, %3;" : "=l"(d) : "l"(a), "l"(b), "l"(c));
    return d;
}
__device__ __forceinline__ float hadd2_(ull a) {
    unsigned lo, hi;
    asm("mov.b64 {%0, %1}, %2;" : "=r"(lo), "=r"(hi) : "l"(a));
    return __uint_as_float(lo) + __uint_as_float(hi);
}
__device__ __forceinline__ void mma_bf16(float c[4],
    uint a0, uint a1, uint a2, uint a3, uint b0, uint b1)
{
    asm volatile(
        "mma.sync.aligned.m16n8k16.row.col.f32.bf16.bf16.f32 "
        "{%0,%1,%2,%3},{%4,%5,%6,%7},{%8,%9},{%0,%1,%2,%3};"
        : "+f"(c[0]), "+f"(c[1]), "+f"(c[2]), "+f"(c[3])
        : "r"(a0), "r"(a1), "r"(a2), "r"(a3), "r"(b0), "r"(b1));
}
__device__ __forceinline__ void ldsm_x4(uint& r0, uint& r1, uint& r2, uint& r3,
                                        const void* p)
{
    uint a = (uint)__cvta_generic_to_shared(p);
    asm volatile("ldmatrix.sync.aligned.m8n8.x4.shared.b16 {%0,%1,%2,%3},[%4];"
                 : "=r"(r0), "=r"(r1), "=r"(r2), "=r"(r3) : "r"(a));
}
__device__ __forceinline__ void ldsm_x2t(uint& r0, uint& r1, const void* p)
{
    uint a = (uint)__cvta_generic_to_shared(p);
    asm volatile("ldmatrix.sync.aligned.m8n8.x2.trans.shared.b16 {%0,%1},[%2];"
                 : "=r"(r0), "=r"(r1) : "r"(a));
}
__device__ __forceinline__ void split4(float4 v, uint& h01, uint& h23,
                                       uint& l01, uint& l23)
{
    __nv_bfloat162 h01b = __floats2bfloat162_rn(v.x, v.y);
    __nv_bfloat162 h23b = __floats2bfloat162_rn(v.z, v.w);
    float r0 = v.x - __bfloat162float(h01b.x);
    float r1 = v.y - __bfloat162float(h01b.y);
    float r2 = v.z - __bfloat162float(h23b.x);
    float r3 = v.w - __bfloat162float(h23b.y);
    __nv_bfloat162 l01b = __floats2bfloat162_rn(r0, r1);
    __nv_bfloat162 l23b = __floats2bfloat162_rn(r2, r3);
    h01 = *(uint*)&h01b;  h23 = *(uint*)&h23b;
    l01 = *(uint*)&l01b;  l23 = *(uint*)&l23b;
}

#define A_STRIDE 12
#define B_STRIDE 68

__global__ __launch_bounds__(256) void gemm_tc(
    const float* __restrict__ Aext, size_t Aoff,
    const float* __restrict__ W0, const float* __restrict__ W1,
    const float* __restrict__ W2,
    float* __restrict__ Cext, size_t Coff, int nblk,
    int M, int N, int K, int act)
{
    const float* A = Aext ? Aext : (const float*)g_scratch + Aoff;
    const int which = blockIdx.x / nblk;
    const float* W = (which == 0) ? W0 : (which == 1) ? W1 : W2;
    float* C = Cext ? Cext : g_scratch + Coff + (size_t)which * NM;

    __shared__ __align__(16) uint As[2][2][128][A_STRIDE];
    __shared__ __align__(16) uint Bs[2][2][16][B_STRIDE];

    const int tid  = threadIdx.x;
    const int brow = blockIdx.y * 128;
    const int bcol = (blockIdx.x % nblk) * 128;
    const int lane = tid & 31;
    const int warp = tid >> 5;
    const int wm   = warp >> 2;
    const int wn   = warp & 3;
    const int gid  = lane >> 2;
    const int tig  = lane & 3;
    const int am0 = tid >> 2;
    const int ak0 = (tid & 3) << 2;
    const int bk0 = tid >> 5;
    const int bn0 = (tid & 31) << 2;

    const float* ApA = A + (size_t)(brow + am0) * K + ak0;
    const float* ApB = ApA + (size_t)64 * K;
    const float* BpA = W + (size_t)bk0 * N + bcol + bn0;
    const float* BpB = BpA + (size_t)8 * N;

    float acc[4][4][4];
#pragma unroll
    for (int i = 0; i < 4; i++)
#pragma unroll
        for (int j = 0; j < 4; j++)
#pragma unroll
            for (int c = 0; c < 4; c++) acc[i][j][c] = 0.f;

    const int a_lrow = lane & 15;
    const int a_koff = (lane >> 4) * 4;
    const int b_lrow = lane & 15;

    float4 avA, avB, bvA, bvB;
    avA = *(const float4*)(ApA);
    avB = *(const float4*)(ApB);
    bvA = *(const float4*)(BpA);
    bvB = *(const float4*)(BpB);
    {
        uint h01, h23, l01, l23;
        split4(avA, h01, h23, l01, l23);
        *(uint2*)&As[0][0][am0][ak0 >> 1]      = make_uint2(h01, h23);
        *(uint2*)&As[0][1][am0][ak0 >> 1]      = make_uint2(l01, l23);
        split4(avB, h01, h23, l01, l23);
        *(uint2*)&As[0][0][am0 + 64][ak0 >> 1] = make_uint2(h01, h23);
        *(uint2*)&As[0][1][am0 + 64][ak0 >> 1] = make_uint2(l01, l23);
        split4(bvA, h01, h23, l01, l23);
        *(uint2*)&Bs[0][0][bk0][bn0 >> 1]      = make_uint2(h01, h23);
        *(uint2*)&Bs[0][1][bk0][bn0 >> 1]      = make_uint2(l01, l23);
        split4(bvB, h01, h23, l01, l23);
        *(uint2*)&Bs[0][0][bk0 + 8][bn0 >> 1]  = make_uint2(h01, h23);
        *(uint2*)&Bs[0][1][bk0 + 8][bn0 >> 1]  = make_uint2(l01, l23);
    }
    __syncthreads();

    const int nk = K >> 4;
    for (int kt = 0; kt < nk; kt++) {
        const int buf = kt & 1;
        if (kt + 1 < nk) {
            const int ko = (kt + 1) << 4;
            avA = *(const float4*)(ApA + ko);
            avB = *(const float4*)(ApB + ko);
            bvA = *(const float4*)(BpA + (size_t)ko * N);
            bvB = *(const float4*)(BpB + (size_t)ko * N);
        }
        uint Ah[4][4], Al[4][4], Bh[4][2], Bl[4][2];
#pragma unroll
        for (int mt = 0; mt < 4; mt++) {
            int row = wm * 64 + mt * 16 + a_lrow;
            ldsm_x4(Ah[mt][0], Ah[mt][1], Ah[mt][2], Ah[mt][3],
                    &As[buf][0][row][a_koff]);
            ldsm_x4(Al[mt][0], Al[mt][1], Al[mt][2], Al[mt][3],
                    &As[buf][1][row][a_koff]);
        }
#pragma unroll
        for (int nt = 0; nt < 4; nt++) {
            int nu = wn * 16 + nt * 4;
            ldsm_x2t(Bh[nt][0], Bh[nt][1], &Bs[buf][0][b_lrow][nu]);
            ldsm_x2t(Bl[nt][0], Bl[nt][1], &Bs[buf][1][b_lrow][nu]);
        }
#pragma unroll
        for (int mt = 0; mt < 4; mt++) {
#pragma unroll
            for (int nt = 0; nt < 4; nt++) {
                mma_bf16(acc[mt][nt], Ah[mt][0], Ah[mt][1], Ah[mt][2], Ah[mt][3],
                         Bh[nt][0], Bh[nt][1]);
                mma_bf16(acc[mt][nt], Ah[mt][0], Ah[mt][1], Ah[mt][2], Ah[mt][3],
                         Bl[nt][0], Bl[nt][1]);
                mma_bf16(acc[mt][nt], Al[mt][0], Al[mt][1], Al[mt][2], Al[mt][3],
                         Bh[nt][0], Bh[nt][1]);
            }
        }
        if (kt + 1 < nk) {
            const int nb = buf ^ 1;
            uint h01, h23, l01, l23;
            split4(avA, h01, h23, l01, l23);
            *(uint2*)&As[nb][0][am0][ak0 >> 1]      = make_uint2(h01, h23);
            *(uint2*)&As[nb][1][am0][ak0 >> 1]      = make_uint2(l01, l23);
            split4(avB, h01, h23, l01, l23);
            *(uint2*)&As[nb][0][am0 + 64][ak0 >> 1] = make_uint2(h01, h23);
            *(uint2*)&As[nb][1][am0 + 64][ak0 >> 1] = make_uint2(l01, l23);
            split4(bvA, h01, h23, l01, l23);
            *(uint2*)&Bs[nb][0][bk0][bn0 >> 1]      = make_uint2(h01, h23);
            *(uint2*)&Bs[nb][1][bk0][bn0 >> 1]      = make_uint2(l01, l23);
            split4(bvB, h01, h23, l01, l23);
            *(uint2*)&Bs[nb][0][bk0 + 8][bn0 >> 1]  = make_uint2(h01, h23);
            *(uint2*)&Bs[nb][1][bk0 + 8][bn0 >> 1]  = make_uint2(l01, l23);
            __syncthreads();
        }
    }
#pragma unroll
    for (int mt = 0; mt < 4; mt++) {
        int row0 = brow + wm * 64 + mt * 16 + gid;
#pragma unroll
        for (int nt = 0; nt < 4; nt++) {
            int col0 = bcol + wn * 32 + nt * 8 + 2 * tig;
            float c0 = acc[mt][nt][0], c1 = acc[mt][nt][1];
            float c2 = acc[mt][nt][2], c3 = acc[mt][nt][3];
            if (act == 1) {
                c0 *= sigmoidf_(c0); c1 *= sigmoidf_(c1);
                c2 *= sigmoidf_(c2); c3 *= sigmoidf_(c3);
            } else if (act == 2) {
                c0 = sigmoidf_(c0); c1 = sigmoidf_(c1);
                c2 = sigmoidf_(c2); c3 = sigmoidf_(c3);
            }
            *(float2*)(C + (size_t)row0 * N + col0)       = make_float2(c0, c1);
            *(float2*)(C + (size_t)(row0 + 8) * N + col0) = make_float2(c2, c3);
        }
    }
}

__global__ __launch_bounds__(256) void ab_kernel(
    const float* __restrict__ x,
    const float* __restrict__ Wa, const float* __restrict__ ba,
    const float* __restrict__ Wb, const float* __restrict__ bb)
{
    int row  = blockIdx.x * 8 + (threadIdx.x >> 5);
    int lane = threadIdx.x & 31;
    const float* xr = x + (size_t)row * DDIM;
    const float* W  = (lane < 16) ? Wa : Wb;
    int h = lane & 15;
    float s0 = 0.f, s1 = 0.f, s2 = 0.f, s3 = 0.f;
#pragma unroll 4
    for (int i = 0; i < DDIM; i += 4) {
        s0 = fmaf(xr[i + 0], W[(i + 0) * HDIM + h], s0);
        s1 = fmaf(xr[i + 1], W[(i + 1) * HDIM + h], s1);
        s2 = fmaf(xr[i + 2], W[(i + 2) * HDIM + h], s2);
        s3 = fmaf(xr[i + 3], W[(i + 3) * HDIM + h], s3);
    }
    float s = (s0 + s1) + (s2 + s3);
    if (lane < 16) {
        float sg = sigmoidf_(s + ba[h]);
        g_scratch[OF_A + (size_t)row * HDIM + h] = fminf(fmaxf(sg, 0.1f), 1.0f);
    } else {
        float sg = sigmoidf_(s + bb[h]);
        g_scratch[OF_B + (size_t)row * HDIM + h] = fminf(sg, 1.0f);
    }
}

__global__ __launch_bounds__(512) void conv_kernel(
    const float* __restrict__ qcw, const float* __restrict__ qcb,
    const float* __restrict__ kcw, const float* __restrict__ kcb,
    const float* __restrict__ vcw, const float* __restrict__ vcb)
{
    int which = blockIdx.y;
    const float* w;
    const float* bias;
    size_t pre_off, out_off;
    int do_norm;
    if (which == 0) { w = qcw; bias = qcb; pre_off = OF_Q; out_off = OF_QN; do_norm = 1; }
    else if (which == 1) { w = kcw; bias = kcb; pre_off = OF_K; out_off = OF_KN; do_norm = 1; }
    else { w = vcw; bias = vcb; pre_off = OF_V; out_off = OF_VN; do_norm = 0; }

    const float* pre = (const float*)g_scratch + pre_off;
    float*       out = g_scratch + out_off;
    int row  = blockIdx.x;
    int t    = row & (TDIM - 1);
    int lane = threadIdx.x & 31;
    int h    = threadIdx.x >> 5;
    int c0   = h * 64 + lane;
    int c1   = c0 + 32;

    const float* p = pre + (size_t)row * DDIM;
    float v0 = bias[c0], v1 = bias[c1];
#pragma unroll
    for (int kk = 0; kk < 4; kk++) {
        int dt = kk - 3;
        if (t + dt >= 0) {
            const float* pr = p + (ptrdiff_t)dt * DDIM;
            v0 = fmaf(w[c0 * 4 + kk], pr[c0], v0);
            v1 = fmaf(w[c1 * 4 + kk], pr[c1], v1);
        }
    }
    v0 *= sigmoidf_(v0);
    v1 *= sigmoidf_(v1);
    if (do_norm) {
        float ss = v0 * v0 + v1 * v1;
#pragma unroll
        for (int o = 16; o > 0; o >>= 1) ss += __shfl_xor_sync(0xffffffffu, ss, o);
        float inv = 1.f / fmaxf(sqrtf(ss), 1e-6f);
        v0 *= inv; v1 *= inv;
    }
    out[(size_t)row * DDIM + c0] = v0;
    out[(size_t)row * DDIM + c1] = v1;
}

// ---------------------------------------------------------------------------
// prep_kernel: register-tiled dots + exp2 tables + 4-way ILP substitution.
// ---------------------------------------------------------------------------
__global__ __launch_bounds__(256) void prep_kernel()
{
    extern __shared__ float sm[];
    float* Kc  = sm;
    float* Qv  = sm + 4352;
    float* MM  = sm + 8704;
    float* sLc = sm + 13056;
    float* sLp = sm + 13120;
    float* sbv = sm + 13184;
    float* sbp = sm + 13248;
    float* E2  = sm + 13312;
    float* Ei2 = sm + 13376;
    float* E2p = sm + 13440;
    float* A0  = sm + 13504;
    float* G0  = sm + 13568;

    const float* Qn = g_scratch + OF_QN;
    const float* Kn = g_scratch + OF_KN;
    const float* Vn = g_scratch + OF_VN;
    const float* Al = g_scratch + OF_A;
    const float* Be = g_scratch + OF_B;

    int cid = blockIdx.x;
    int bh = cid >> 6, ci = cid & 63;
    int b = bh >> 4, h = bh & 15;
    int t0c = ci << 6;
    size_t base  = (size_t)b * TDIM * DDIM + (size_t)h * 64 + (size_t)t0c * DDIM;
    size_t abase = (size_t)b * TDIM * HDIM + h + (size_t)t0c * HDIM;
    int tid = threadIdx.x;

    if (tid < 64) {
        sLc[tid] = log2f(Al[abase + (size_t)tid * HDIM]);
        sbv[tid] = Be[abase + (size_t)tid * HDIM];
    }
    __syncthreads();
    if (tid == 0) {
        float run = 0.f;
        for (int i = 0; i < 64; i++) { sLp[i] = run; run += sLc[i]; sLc[i] = run; }
    }
    {
        int row = tid >> 4;
        int col = (tid & 15) << 2;
        for (int rr = 0; rr < 4; rr++) {
            int r = row + rr * 16;
            *(float4*)&Kc[r * 68 + col] = *(const float4*)(Kn + base + (size_t)r * DDIM + col);
            *(float4*)&Qv[r * 68 + col] = *(const float4*)(Qn + base + (size_t)r * DDIM + col);
        }
    }
    __syncthreads();
    if (tid < 64) {
        float lc = sLc[tid], lp = sLp[tid];
        sbp[tid] = sbv[tid] * exp2f(lp);
        E2[tid]  = exp2f(lc + 104.f);
        Ei2[tid] = exp2f(-lc - 104.f);
        E2p[tid] = exp2f(lp + 104.f);
        A0[tid]  = exp2f(lc);
        G0[tid]  = exp2f(sLc[63] - lc);
    }
    __syncthreads();

    float* Pg  = g_scratch + OF_PG  + (size_t)cid * 4096;
    float* AQg = g_scratch + OF_AQG + (size_t)cid * 4096;
    float* Gg  = g_scratch + OF_GKT + (size_t)cid * 4096;
    float* Wg  = g_scratch + OF_WTG + (size_t)cid * 4096;
    float* Ug  = g_scratch + OF_UVT + (size_t)cid * 4096;

    for (int kq = 0; kq < 16; kq++) {
        int e = kq * 256 + tid;
        int t = e >> 6, i = e & 63;
        AQg[e] = A0[t] * Qv[t * 68 + i];
        Gg[e]  = G0[i] * Kc[i * 68 + t];
    }

    {
        int tt = tid >> 4, ti = tid & 15;
        int t0 = tt << 2, i0 = ti << 2;
        if (i0 <= t0 + 3) {
            ull acc2[4][4];
#pragma unroll
            for (int a = 0; a < 4; a++)
#pragma unroll
                for (int bb2 = 0; bb2 < 4; bb2++) acc2[a][bb2] = 0ull;
#pragma unroll 8
            for (int m = 0; m < 64; m += 2) {
                ull qr[4], kr[4];
#pragma unroll
                for (int a = 0; a < 4; a++) qr[a] = *(ull*)&Qv[(t0 + a) * 68 + m];
#pragma unroll
                for (int bb2 = 0; bb2 < 4; bb2++) kr[bb2] = *(ull*)&Kc[(i0 + bb2) * 68 + m];
#pragma unroll
                for (int a = 0; a < 4; a++)
#pragma unroll
                    for (int bb2 = 0; bb2 < 4; bb2++)
                        acc2[a][bb2] = fma2_(qr[a], kr[bb2], acc2[a][bb2]);
            }
#pragma unroll
            for (int a = 0; a < 4; a++) {
                int t = t0 + a;
                float4 v;
                float e2t = E2[t];
                v.x = (i0 + 0 <= t) ? e2t * Ei2[i0 + 0] * hadd2_(acc2[a][0]) : 0.f;
                v.y = (i0 + 1 <= t) ? e2t * Ei2[i0 + 1] * hadd2_(acc2[a][1]) : 0.f;
                v.z = (i0 + 2 <= t) ? e2t * Ei2[i0 + 2] * hadd2_(acc2[a][2]) : 0.f;
                v.w = (i0 + 3 <= t) ? e2t * Ei2[i0 + 3] * hadd2_(acc2[a][3]) : 0.f;
                *(float4*)(Pg + t * 64 + i0) = v;
            }
        } else {
            float4 z = make_float4(0.f, 0.f, 0.f, 0.f);
#pragma unroll
            for (int a = 0; a < 4; a++) *(float4*)(Pg + (t0 + a) * 64 + i0) = z;
        }
    }
    __syncthreads();
    {
        int row = tid >> 4;
        int col = (tid & 15) << 2;
        for (int rr = 0; rr < 4; rr++) {
            int r = row + rr * 16;
            *(float4*)&Qv[r * 68 + col] = *(const float4*)(Vn + base + (size_t)r * DDIM + col);
        }
    }
    __syncthreads();
    {
        int tI = tid >> 4, tJ = tid & 15;
        int i0 = tI << 2, j0 = tJ << 2;
        if (j0 <= i0 + 3) {
            ull acc2[4][4];
#pragma unroll
            for (int a = 0; a < 4; a++)
#pragma unroll
                for (int bb2 = 0; bb2 < 4; bb2++) acc2[a][bb2] = 0ull;
#pragma unroll 8
            for (int m = 0; m < 64; m += 2) {
                ull ir[4], jr[4];
#pragma unroll
                for (int a = 0; a < 4; a++) ir[a] = *(ull*)&Kc[(i0 + a) * 68 + m];
#pragma unroll
                for (int bb2 = 0; bb2 < 4; bb2++) jr[bb2] = *(ull*)&Kc[(j0 + bb2) * 68 + m];
#pragma unroll
                for (int a = 0; a < 4; a++)
#pragma unroll
                    for (int bb2 = 0; bb2 < 4; bb2++)
                        acc2[a][bb2] = fma2_(ir[a], jr[bb2], acc2[a][bb2]);
            }
#pragma unroll
            for (int a = 0; a < 4; a++) {
                int i = i0 + a;
                float bi = sbv[i] * E2p[i];
#pragma unroll
                for (int bb2 = 0; bb2 < 4; bb2++) {
                    int j = j0 + bb2;
                    if (j < i)
                        MM[i * 68 + j] = bi * Ei2[j] * hadd2_(acc2[a][bb2]);
                }
            }
        }
    }
    __syncthreads();

    float xr[64];
    if (tid < 128) {
        int c = tid;
        if (c < 64) {
#pragma unroll
            for (int i = 0; i < 64; i++) xr[i] = sbv[i] * Qv[i * 68 + c];
        } else {
            int k = c - 64;
#pragma unroll
            for (int i = 0; i < 64; i++) xr[i] = sbp[i] * Kc[i * 68 + k];
        }
#pragma unroll
        for (int i = 1; i < 64; i++) {
            float a0 = 0.f, a1 = 0.f, a2 = 0.f, a3 = 0.f;
            int j = 0;
#pragma unroll
            for (; j + 3 < i; j += 4) {
                a0 = fmaf(MM[i * 68 + j],     xr[j],     a0);
                a1 = fmaf(MM[i * 68 + j + 1], xr[j + 1], a1);
                a2 = fmaf(MM[i * 68 + j + 2], xr[j + 2], a2);
                a3 = fmaf(MM[i * 68 + j + 3], xr[j + 3], a3);
            }
#pragma unroll
            for (; j < i; j++) a0 = fmaf(MM[i * 68 + j], xr[j], a0);
            xr[i] -= ((a0 + a1) + (a2 + a3));
        }
    }
    __syncthreads();
    if (tid < 64) {
        int c = tid;
#pragma unroll
        for (int i = 0; i < 64; i++) Qv[c * 68 + i] = xr[i];
    } else if (tid < 128) {
        int k = tid - 64;
#pragma unroll
        for (int i = 0; i < 64; i++) MM[i * 68 + k] = xr[i];
    }
    __syncthreads();
    for (int kq = 0; kq < 16; kq++) {
        int e = kq * 256 + tid;
        { int c = e >> 6, i = e & 63; Ug[e] = Qv[c * 68 + i]; }
        { int i = e >> 6, kk = e & 63; Wg[e] = MM[i * 68 + kk]; }
    }
    if (tid == 0) g_scratch[OF_ACG + cid] = exp2f(sLc[63]);
}

// ---------------------------------------------------------------------------
// scan_kernel (round-14 proven version): 128 CTAs, 128 threads.
// ---------------------------------------------------------------------------
__global__ __launch_bounds__(128) void scan_kernel()
{
    extern __shared__ float sm[];
    float* mW  = sm;
    float* mAQ = sm + 4352;
    float* mP  = sm + 8704;
    float* mG  = sm + 13056;
    float* S_T = sm + 17408;
    float* U_T = sm + 18496;

    int blk = blockIdx.x;
    int bh = blk >> 2, cq = blk & 3;
    int c0 = cq << 4;
    int b = bh >> 4, h = bh & 15;
    size_t obase = (size_t)b * TDIM * DDIM + (size_t)h * 64;
    int tid = threadIdx.x;
    int cc = tid & 15, grp = tid >> 4;

    for (int e = tid; e < 16 * 68; e += 128) S_T[e] = 0.f;
    __syncthreads();

    float* O = g_scratch + OF_O;

    for (int ch = 0; ch < NCHUNK; ch++) {
        int cid = bh * 64 + ch;
        const float* Wg  = g_scratch + OF_WTG + (size_t)cid * 4096;
        const float* AQg = g_scratch + OF_AQG + (size_t)cid * 4096;
        const float* Pg  = g_scratch + OF_PG  + (size_t)cid * 4096;
        const float* Gg  = g_scratch + OF_GKT + (size_t)cid * 4096;
        const float* Ug  = g_scratch + OF_UVT + (size_t)cid * 4096;

        for (int kq = 0; kq < 8; kq++) {
            int e4 = kq * 128 + tid;
            int r = e4 >> 4, c4 = (e4 & 15) << 2;
            *(float4*)&mW[r * 68 + c4]  = *(const float4*)(Wg  + r * 64 + c4);
            *(float4*)&mAQ[r * 68 + c4] = *(const float4*)(AQg + r * 64 + c4);
            *(float4*)&mP[r * 68 + c4]  = *(const float4*)(Pg  + r * 64 + c4);
            *(float4*)&mG[r * 68 + c4]  = *(const float4*)(Gg  + r * 64 + c4);
        }
        for (int kq = 0; kq < 2; kq++) {
            int e4 = kq * 128 + tid;
            int r = e4 >> 4, c4 = (e4 & 15) << 2;
            *(float4*)&U_T[r * 68 + c4] = *(const float4*)(Ug + (size_t)(c0 + r) * 64 + c4);
        }
        float AC = g_scratch[OF_ACG + cid];
        __syncthreads();

        {
            ull aU[8][2];
#pragma unroll
            for (int ii = 0; ii < 8; ii++) { aU[ii][0] = 0; aU[ii][1] = 0; }
#pragma unroll
            for (int k4 = 0; k4 < 16; k4++) {
                ull s01 = *(ull*)&S_T[cc * 68 + k4 * 4];
                ull s23 = *(ull*)&S_T[cc * 68 + k4 * 4 + 2];
#pragma unroll
                for (int ii = 0; ii < 8; ii++) {
                    int i = grp * 8 + ii;
                    aU[ii][0] = fma2_(*(ull*)&mW[i * 68 + k4 * 4],     s01, aU[ii][0]);
                    aU[ii][1] = fma2_(*(ull*)&mW[i * 68 + k4 * 4 + 2], s23, aU[ii][1]);
                }
            }
#pragma unroll
            for (int ii = 0; ii < 8; ii++) {
                int i = grp * 8 + ii;
                U_T[cc * 68 + i] -= (hadd2_(aU[ii][0]) + hadd2_(aU[ii][1]));
            }
        }
        float oacc[8];
        {
            ull aO[8][2];
#pragma unroll
            for (int ii = 0; ii < 8; ii++) { aO[ii][0] = 0; aO[ii][1] = 0; }
#pragma unroll
            for (int k4 = 0; k4 < 16; k4++) {
                ull s01 = *(ull*)&S_T[cc * 68 + k4 * 4];
                ull s23 = *(ull*)&S_T[cc * 68 + k4 * 4 + 2];
#pragma unroll
                for (int ii = 0; ii < 8; ii++) {
                    int t = grp * 8 + ii;
                    aO[ii][0] = fma2_(*(ull*)&mAQ[t * 68 + k4 * 4],     s01, aO[ii][0]);
                    aO[ii][1] = fma2_(*(ull*)&mAQ[t * 68 + k4 * 4 + 2], s23, aO[ii][1]);
                }
            }
#pragma unroll
            for (int ii = 0; ii < 8; ii++)
                oacc[ii] = hadd2_(aO[ii][0]) + hadd2_(aO[ii][1]);
        }
        __syncthreads();
        {
            ull aO[8][2];
#pragma unroll
            for (int ii = 0; ii < 8; ii++) { aO[ii][0] = 0; aO[ii][1] = 0; }
#pragma unroll
            for (int k4 = 0; k4 < 16; k4++) {
                ull u01 = *(ull*)&U_T[cc * 68 + k4 * 4];
                ull u23 = *(ull*)&U_T[cc * 68 + k4 * 4 + 2];
#pragma unroll
                for (int ii = 0; ii < 8; ii++) {
                    int t = grp * 8 + ii;
                    aO[ii][0] = fma2_(*(ull*)&mP[t * 68 + k4 * 4],     u01, aO[ii][0]);
                    aO[ii][1] = fma2_(*(ull*)&mP[t * 68 + k4 * 4 + 2], u23, aO[ii][1]);
                }
            }
#pragma unroll
            for (int ii = 0; ii < 8; ii++) {
                int t = grp * 8 + ii;
                float ov = oacc[ii] + hadd2_(aO[ii][0]) + hadd2_(aO[ii][1]);
                O[obase + (size_t)(ch * 64 + t) * DDIM + c0 + cc] = ov;
            }
        }
        {
            ull aS[8][2];
#pragma unroll
            for (int ii = 0; ii < 8; ii++) { aS[ii][0] = 0; aS[ii][1] = 0; }
#pragma unroll
            for (int k4 = 0; k4 < 16; k4++) {
                ull u01 = *(ull*)&U_T[cc * 68 + k4 * 4];
                ull u23 = *(ull*)&U_T[cc * 68 + k4 * 4 + 2];
#pragma unroll
                for (int ii = 0; ii < 8; ii++) {
                    int r = grp * 8 + ii;
                    aS[ii][0] = fma2_(*(ull*)&mG[r * 68 + k4 * 4],     u01, aS[ii][0]);
                    aS[ii][1] = fma2_(*(ull*)&mG[r * 68 + k4 * 4 + 2], u23, aS[ii][1]);
                }
            }
#pragma unroll
            for (int ii = 0; ii < 8; ii++) {
                int r = grp * 8 + ii;
                S_T[cc * 68 + r] = AC * S_T[cc * 68 + r]
                                   + hadd2_(aS[ii][0]) + hadd2_(aS[ii][1]);
            }
        }
        __syncthreads();
    }
}

__global__ __launch_bounds__(512) void post_kernel(const float* __restrict__ rms_w)
{
    const float* O  = g_scratch + OF_O;
    const float* G  = g_scratch + OF_G;
    float*       Og = g_scratch + OF_OG;
    int row  = blockIdx.x;
    int lane = threadIdx.x & 31;
    int h    = threadIdx.x >> 5;
    size_t i0 = (size_t)row * DDIM + h * 64 + lane;
    float v0 = O[i0], v1 = O[i0 + 32];
    float ss = v0 * v0 + v1 * v1;
#pragma unroll
    for (int o = 16; o > 0; o >>= 1) ss += __shfl_xor_sync(0xffffffffu, ss, o);
    float inv = rsqrtf(ss * (1.f / 64.f) + 1e-6f);
    v0 = v0 * inv * rms_w[h * 64 + lane]      * G[i0];
    v1 = v1 * inv * rms_w[h * 64 + lane + 32] * G[i0 + 32];
    Og[i0]      = v0;
    Og[i0 + 32] = v1;
}

extern "C" void kernel_launch(void* const* d_in, const int* in_sizes, int n_in,
                              void* d_out, int out_size)
{
    (void)in_sizes; (void)n_in; (void)out_size;
    const float* x   = (const float*)d_in[0];
    const float* Wq  = (const float*)d_in[1];
    const float* Wk  = (const float*)d_in[2];
    const float* Wv  = (const float*)d_in[3];
    const float* Wo  = (const float*)d_in[4];
    const float* Wa  = (const float*)d_in[5];
    const float* ba  = (const float*)d_in[6];
    const float* Wb  = (const float*)d_in[7];
    const float* bb  = (const float*)d_in[8];
    const float* Wgd = (const float*)d_in[9];
    const float* Wgu = (const float*)d_in[10];
    const float* rms = (const float*)d_in[11];
    const float* qcw = (const float*)d_in[12];
    const float* qcb = (const float*)d_in[13];
    const float* kcw = (const float*)d_in[14];
    const float* kcb = (const float*)d_in[15];
    const float* vcw = (const float*)d_in[16];
    const float* vcb = (const float*)d_in[17];
    float* out = (float*)d_out;

    cudaFuncSetAttribute(prep_kernel, cudaFuncAttributeMaxDynamicSharedMemorySize, 57344);
    cudaFuncSetAttribute(scan_kernel, cudaFuncAttributeMaxDynamicSharedMemorySize, 81920);

    // 1) alpha/beta
    ab_kernel<<<MROWS / 8, 256>>>(x, Wa, ba, Wb, bb);
    // 2) fused QKV projection
    {
        dim3 gqkv(24, MROWS / 128);
        gemm_tc<<<gqkv, 256>>>(x, 0, Wq, Wk, Wv, nullptr, OF_Q, 8,
                               MROWS, 1024, 1024, 0);
    }
    // 3) conv
    {
        dim3 gc(MROWS, 3);
        conv_kernel<<<gc, 512>>>(qcw, qcb, kcw, kcb, vcw, vcb);
    }
    // 4) chunk prep (parallel)  <-- ncu capture slot
    prep_kernel<<<NCH_TOT, 256, 57344>>>();
    // 5) chunk scan
    scan_kernel<<<BDIM * HDIM * 4, 128, 81920>>>();
    // 6-7) gate MLP
    {
        dim3 g512g(4, MROWS / 128);
        gemm_tc<<<g512g, 256>>>(x, 0, Wgd, Wgd, Wgd, nullptr, OF_XG, 4,
                                MROWS, 512, 1024, 1);
    }
    {
        dim3 g1024g(8, MROWS / 128);
        gemm_tc<<<g1024g, 256>>>(nullptr, OF_XG, Wgu, Wgu, Wgu, nullptr, OF_G, 8,
                                 MROWS, 1024, 512, 2);
    }
    // 8) RMSNorm + gate
    post_kernel<<<MROWS, 512>>>(rms);
    // 9) output projection
    {
        dim3 g1024g(8, MROWS / 128);
        gemm_tc<<<g1024g, 256>>>(nullptr, OF_OG, Wo, Wo, Wo, out, 0, 8,
                                 MROWS, 1024, 1024, 0);
    }
}